// round 2
// baseline (speedup 1.0000x reference)
#include <cuda_runtime.h>
#include <cuda_bf16.h>

// ---------------------------------------------------------------------------
// GnnEncoder: 3-layer GraphSAGE (mean aggr) + ReLU + LayerNorm, fp32.
//   h1 = LN(relu(mean(x)@Wl1^T + bl1 + x@Wr1^T))
//   h2 = LN(relu(mean(h1)@Wl2^T + bl2 + h1@Wr2^T))
//   out = mean(h2)@Wl3^T + bl3 + h2@Wr3^T
// Strategy: build CSR-by-dst once per launch (no float atomics), warp-per-node
// mean aggregation out of L2, fused GEMM (K=2x128) + bias/ReLU/LN epilogue.
// R1 fix: K-tile loop was 16 tiles (K=256 per operand) instead of 8 (128 per
// operand) -> read past row ends -> garbage. Now t<8, switch at t==4.
// ---------------------------------------------------------------------------

static constexpr int NN = 50000;
static constexpr int EE = 800000;
static constexpr int C  = 128;

// scratch (static __device__ allocations: allowed)
__device__ float g_mean[NN * C];
__device__ float g_h1[NN * C];
__device__ float g_h2[NN * C];
__device__ int   g_src[EE];
__device__ int   g_dst[EE];
__device__ int   g_csr[EE];
__device__ int   g_off[NN + 1];
__device__ int   g_cnt[NN];
__device__ int   g_cur[NN];
__device__ float g_invc[NN];
__device__ int   g_is64;

// --------------------------- index prep ------------------------------------

// Detect int64 vs int32 storage of edge_index: values are in [0, 50000), so
// for int64 little-endian every odd 32-bit word is 0. Probability of 512
// random int32 node ids all being zero is ~0.
__global__ void k_detect(const unsigned* __restrict__ buf) {
    int nz = 0;
    for (int i = threadIdx.x; i < 512; i += blockDim.x)
        if (buf[2 * i + 1] != 0u) nz = 1;
    nz = __syncthreads_or(nz);
    if (threadIdx.x == 0) g_is64 = (nz == 0) ? 1 : 0;
}

__global__ void k_convert(const void* __restrict__ buf, int E) {
    int e = blockIdx.x * blockDim.x + threadIdx.x;
    if (e >= E) return;
    if (g_is64) {
        const long long* p = (const long long*)buf;
        g_src[e] = (int)p[e];
        g_dst[e] = (int)p[E + e];
    } else {
        const int* p = (const int*)buf;
        g_src[e] = p[e];
        g_dst[e] = p[E + e];
    }
}

__global__ void k_zero(int n) {
    int i = blockIdx.x * blockDim.x + threadIdx.x;
    if (i < n) { g_cnt[i] = 0; g_cur[i] = 0; }
}

__global__ void k_hist(int E) {
    int e = blockIdx.x * blockDim.x + threadIdx.x;
    if (e < E) atomicAdd(&g_cnt[g_dst[e]], 1);
}

// single-block exclusive scan of g_cnt -> g_off (n up to ~50k, 1024 threads)
__global__ void k_scan(int n) {
    __shared__ int sh[1024];
    __shared__ int s_carry;
    const int tid = threadIdx.x;
    if (tid == 0) s_carry = 0;
    __syncthreads();
    for (int base = 0; base < n; base += 1024) {
        int c = s_carry;
        int i = base + tid;
        int v = (i < n) ? g_cnt[i] : 0;
        sh[tid] = v;
        __syncthreads();
        for (int off = 1; off < 1024; off <<= 1) {
            int t = (tid >= off) ? sh[tid - off] : 0;
            __syncthreads();
            sh[tid] += t;
            __syncthreads();
        }
        int incl = sh[tid];
        if (i < n) g_off[i] = c + incl - v;   // exclusive
        if (tid == 0) s_carry = c + sh[1023];
        __syncthreads();
    }
    if (tid == 0) g_off[n] = s_carry;
}

__global__ void k_invc(int n) {
    int i = blockIdx.x * blockDim.x + threadIdx.x;
    if (i < n) {
        int cnt = g_cnt[i];
        g_invc[i] = 1.0f / (float)(cnt > 0 ? cnt : 1);
    }
}

__global__ void k_scatter(int E) {
    int e = blockIdx.x * blockDim.x + threadIdx.x;
    if (e >= E) return;
    int d = g_dst[e];
    int p = atomicAdd(&g_cur[d], 1);
    g_csr[g_off[d] + p] = g_src[e];
}

// --------------------------- aggregation -----------------------------------
// warp-per-node mean of neighbor feature rows (128 f32 = float4 per lane)
// insel: 0 -> external x, 1 -> g_h1, 2 -> g_h2. Output always g_mean.
__global__ __launch_bounds__(256) void k_agg(const float* __restrict__ xext,
                                             int insel, int n) {
    const float* xin = (insel == 0) ? xext : (insel == 1) ? g_h1 : g_h2;
    int warp = (blockIdx.x * blockDim.x + threadIdx.x) >> 5;
    int lane = threadIdx.x & 31;
    if (warp >= n) return;
    int s0 = g_off[warp], s1 = g_off[warp + 1];
    const float4* xin4 = (const float4*)xin;
    float4 acc = make_float4(0.f, 0.f, 0.f, 0.f);
    int i = s0;
    for (; i + 1 < s1; i += 2) {
        int a = g_csr[i], b = g_csr[i + 1];
        float4 va = xin4[a * 32 + lane];
        float4 vb = xin4[b * 32 + lane];
        acc.x += va.x + vb.x; acc.y += va.y + vb.y;
        acc.z += va.z + vb.z; acc.w += va.w + vb.w;
    }
    if (i < s1) {
        int a = g_csr[i];
        float4 va = xin4[a * 32 + lane];
        acc.x += va.x; acc.y += va.y; acc.z += va.z; acc.w += va.w;
    }
    float ic = g_invc[warp];
    acc.x *= ic; acc.y *= ic; acc.z *= ic; acc.w *= ic;
    ((float4*)g_mean)[warp * 32 + lane] = acc;
}

// --------------------------- fused GEMM ------------------------------------
// out[n][j] = sum_k mean[n][k]*Wl[j][k] + sum_k ax[n][k]*Wr[j][k] + bias[j]
// then (optionally) ReLU + LayerNorm(gamma, beta).
// BM=64 rows, BN columns (128 or 64), BK=32, 256 threads.
// tid = ty*32+tx ; each thread: 8 rows (ty*8..) x TN cols (tx*TN..).
// A warp (fixed ty) owns whole rows -> LN row reduction is a warp shuffle.
template <int BN, bool FUSE>
__global__ __launch_bounds__(256) void k_gemm(
    const float* __restrict__ xext, float* __restrict__ outext,
    const float* __restrict__ Wl, const float* __restrict__ Wr,
    const float* __restrict__ bias,
    const float* __restrict__ gamma, const float* __restrict__ beta,
    int axsel, int outsel, int n)
{
    constexpr int BM = 64, BK = 32, TN = BN / 32;
    const float* Am = g_mean;
    const float* Ax = (axsel == 0) ? xext : (axsel == 1) ? g_h1 : g_h2;
    float* out = (outsel == 1) ? g_h1 : (outsel == 2) ? g_h2 : outext;

    __shared__ __align__(16) float As[BK * BM];
    __shared__ __align__(16) float Bs[BK * BN];

    const int tid = threadIdx.x;
    const int tx = tid & 31;
    const int ty = tid >> 5;
    const int rowBase = blockIdx.x * BM;

    float acc[8][TN];
#pragma unroll
    for (int r = 0; r < 8; r++)
#pragma unroll
        for (int c = 0; c < TN; c++) acc[r][c] = 0.f;

    // 8 K-tiles total: t=0..3 -> (mean, Wl), t=4..7 -> (ax, Wr); k0 = (t&3)*32
    for (int t = 0; t < 8; t++) {
        const float* A = (t < 4) ? Am : Ax;
        const float* W = (t < 4) ? Wl : Wr;
        const int k0 = (t & 3) * BK;

        // A tile: As[k][m] (transposed), 64x32 = 512 float4
#pragma unroll
        for (int f = tid; f < (BK * BM / 4); f += 256) {
            int row = f >> 3, kq = f & 7;
            float4 v = make_float4(0.f, 0.f, 0.f, 0.f);
            int gr = rowBase + row;
            if (gr < n) v = *(const float4*)(A + gr * 128 + k0 + kq * 4);
            As[(kq * 4 + 0) * BM + row] = v.x;
            As[(kq * 4 + 1) * BM + row] = v.y;
            As[(kq * 4 + 2) * BM + row] = v.z;
            As[(kq * 4 + 3) * BM + row] = v.w;
        }
        // B tile: Bs[k][j] = W[j][k0+k]
#pragma unroll
        for (int f = tid; f < (BK * BN / 4); f += 256) {
            int j = f >> 3, kq = f & 7;
            float4 v = *(const float4*)(W + j * 128 + k0 + kq * 4);
            Bs[(kq * 4 + 0) * BN + j] = v.x;
            Bs[(kq * 4 + 1) * BN + j] = v.y;
            Bs[(kq * 4 + 2) * BN + j] = v.z;
            Bs[(kq * 4 + 3) * BN + j] = v.w;
        }
        __syncthreads();

#pragma unroll
        for (int kk = 0; kk < BK; kk++) {
            float4 a0 = *(const float4*)(As + kk * BM + ty * 8);
            float4 a1 = *(const float4*)(As + kk * BM + ty * 8 + 4);
            float a[8] = {a0.x, a0.y, a0.z, a0.w, a1.x, a1.y, a1.z, a1.w};
            float b[TN];
            if constexpr (TN == 4) {
                float4 bv = *(const float4*)(Bs + kk * BN + tx * 4);
                b[0] = bv.x; b[1] = bv.y; b[2] = bv.z; b[3] = bv.w;
            } else {
                float2 bv = *(const float2*)(Bs + kk * BN + tx * 2);
                b[0] = bv.x; b[1] = bv.y;
            }
#pragma unroll
            for (int r = 0; r < 8; r++)
#pragma unroll
                for (int c = 0; c < TN; c++) acc[r][c] += a[r] * b[c];
        }
        __syncthreads();
    }

    // epilogue
    float bb[TN], gg[TN], be[TN];
#pragma unroll
    for (int c = 0; c < TN; c++) {
        bb[c] = bias[tx * TN + c];
        if (FUSE) { gg[c] = gamma[tx * TN + c]; be[c] = beta[tx * TN + c]; }
    }

#pragma unroll
    for (int r = 0; r < 8; r++) {
        int gr = rowBase + ty * 8 + r;
        float v[TN];
#pragma unroll
        for (int c = 0; c < TN; c++) v[c] = acc[r][c] + bb[c];
        if constexpr (FUSE) {
            // ReLU
#pragma unroll
            for (int c = 0; c < TN; c++) v[c] = fmaxf(v[c], 0.f);
            // LayerNorm across the 128-wide row (warp = full row)
            float s = 0.f, ss = 0.f;
#pragma unroll
            for (int c = 0; c < TN; c++) { s += v[c]; ss += v[c] * v[c]; }
#pragma unroll
            for (int o = 16; o > 0; o >>= 1) {
                s  += __shfl_xor_sync(0xffffffffu, s, o);
                ss += __shfl_xor_sync(0xffffffffu, ss, o);
            }
            float mu = s * (1.0f / 128.0f);
            float var = ss * (1.0f / 128.0f) - mu * mu;
            float rstd = rsqrtf(var + 1e-5f);
            float4 o4;
            o4.x = (v[0] - mu) * rstd * gg[0] + be[0];
            o4.y = (v[1] - mu) * rstd * gg[1] + be[1];
            o4.z = (v[2] - mu) * rstd * gg[2] + be[2];
            o4.w = (v[3] - mu) * rstd * gg[3] + be[3];
            if (gr < n) *(float4*)(out + gr * 128 + tx * 4) = o4;
        } else {
            float2 o2; o2.x = v[0]; o2.y = v[1];
            if (gr < n) *(float2*)(out + gr * BN + tx * 2) = o2;
        }
    }
}

// --------------------------- launch ----------------------------------------

extern "C" void kernel_launch(void* const* d_in, const int* in_sizes, int n_in,
                              void* d_out, int out_size)
{
    const float* x   = (const float*)d_in[0];
    const void*  ei  = d_in[1];
    const float* Wl1 = (const float*)d_in[2];
    const float* bl1 = (const float*)d_in[3];
    const float* Wr1 = (const float*)d_in[4];
    const float* Wl2 = (const float*)d_in[5];
    const float* bl2 = (const float*)d_in[6];
    const float* Wr2 = (const float*)d_in[7];
    const float* Wl3 = (const float*)d_in[8];
    const float* bl3 = (const float*)d_in[9];
    const float* Wr3 = (const float*)d_in[10];
    const float* g1  = (const float*)d_in[11];
    const float* be1 = (const float*)d_in[12];
    const float* g2  = (const float*)d_in[13];
    const float* be2 = (const float*)d_in[14];

    const int n = in_sizes[0] / C;       // 50000
    const int E = in_sizes[1] / 2;       // 800000

    const int TB = 256;
    // ---- CSR build (once per launch, shared by all 3 layers) ----
    k_detect<<<1, TB>>>((const unsigned*)ei);
    k_convert<<<(E + TB - 1) / TB, TB>>>(ei, E);
    k_zero<<<(n + TB - 1) / TB, TB>>>(n);
    k_hist<<<(E + TB - 1) / TB, TB>>>(E);
    k_scan<<<1, 1024>>>(n);
    k_invc<<<(n + TB - 1) / TB, TB>>>(n);
    k_scatter<<<(E + TB - 1) / TB, TB>>>(E);

    const int aggGrid  = (n + 7) / 8;          // 8 warps/block, warp per node
    const int gemmGrid = (n + 63) / 64;

    // ---- layer 1 ----
    k_agg<<<aggGrid, TB>>>(x, 0, n);
    k_gemm<128, true><<<gemmGrid, TB>>>(x, nullptr, Wl1, Wr1, bl1, g1, be1,
                                        /*axsel=*/0, /*outsel=*/1, n);
    // ---- layer 2 ----
    k_agg<<<aggGrid, TB>>>(x, 1, n);
    k_gemm<128, true><<<gemmGrid, TB>>>(x, nullptr, Wl2, Wr2, bl2, g2, be2,
                                        /*axsel=*/1, /*outsel=*/2, n);
    // ---- layer 3 (64 outputs, no ReLU/LN) ----
    k_agg<<<aggGrid, TB>>>(x, 2, n);
    k_gemm<64, false><<<gemmGrid, TB>>>(x, (float*)d_out, Wl3, Wr3, bl3,
                                        nullptr, nullptr,
                                        /*axsel=*/2, /*outsel=*/3, n);
}

// round 8
// speedup vs baseline: 1.5475x; 1.5475x over previous
#include <cstdint>
#include <cuda_runtime.h>
#include <cuda_bf16.h>

// ---------------------------------------------------------------------------
// GnnEncoder: 3-layer GraphSAGE (mean aggr) + ReLU + LayerNorm.
// R6: all tensors fp32 in memory (exact aggregation); GEMM uses bf16x3
// emulation on tensor cores: v = hi + lo (both bf16), D += Ah*Bh + Ah*Bl + Al*Bh
// with fp32 accumulators -> ~16-bit effective mantissa, rel_err ~1e-5.
// (R5 failed at 5.2e-3: pure-bf16 storage/MMA quantization, threshold 1e-3.)
// ---------------------------------------------------------------------------

static constexpr int NN = 50000;
static constexpr int EE = 800000;
static constexpr int C  = 128;

// scratch (static __device__ allocations: allowed)
__device__ float g_mean[NN * C];
__device__ float g_h1[NN * C];
__device__ float g_h2[NN * C];
__device__ __nv_bfloat16 g_w1h[128 * 256];
__device__ __nv_bfloat16 g_w1l[128 * 256];
__device__ __nv_bfloat16 g_w2h[128 * 256];
__device__ __nv_bfloat16 g_w2l[128 * 256];
__device__ __nv_bfloat16 g_w3h[64 * 256];
__device__ __nv_bfloat16 g_w3l[64 * 256];
__device__ int   g_src[EE];
__device__ int   g_dst[EE];
__device__ int   g_csr[EE];
__device__ int   g_off[NN + 1];
__device__ int   g_cnt[NN];
__device__ int   g_cur[NN];
__device__ float g_invc[NN];
__device__ int   g_is64;

// --------------------------- index prep ------------------------------------

// Detect int64 vs int32 storage of edge_index: node ids < 50000, so for
// int64 little-endian every odd 32-bit word is 0 across 512 samples.
__global__ void k_detect(const unsigned* __restrict__ buf) {
    int nz = 0;
    for (int i = threadIdx.x; i < 512; i += blockDim.x)
        if (buf[2 * i + 1] != 0u) nz = 1;
    nz = __syncthreads_or(nz);
    if (threadIdx.x == 0) g_is64 = (nz == 0) ? 1 : 0;
}

__global__ void k_convert(const void* __restrict__ buf, int E) {
    int e = blockIdx.x * blockDim.x + threadIdx.x;
    if (e >= E) return;
    if (g_is64) {
        const long long* p = (const long long*)buf;
        g_src[e] = (int)p[e];
        g_dst[e] = (int)p[E + e];
    } else {
        const int* p = (const int*)buf;
        g_src[e] = p[e];
        g_dst[e] = p[E + e];
    }
}

__global__ void k_zero(int n) {
    int i = blockIdx.x * blockDim.x + threadIdx.x;
    if (i < n) { g_cnt[i] = 0; g_cur[i] = 0; }
}

__global__ void k_hist(int E) {
    int e = blockIdx.x * blockDim.x + threadIdx.x;
    if (e < E) atomicAdd(&g_cnt[g_dst[e]], 1);
}

// single-block exclusive scan of g_cnt -> g_off
__global__ void k_scan(int n) {
    __shared__ int sh[1024];
    __shared__ int s_carry;
    const int tid = threadIdx.x;
    if (tid == 0) s_carry = 0;
    __syncthreads();
    for (int base = 0; base < n; base += 1024) {
        int c = s_carry;
        int i = base + tid;
        int v = (i < n) ? g_cnt[i] : 0;
        sh[tid] = v;
        __syncthreads();
        for (int off = 1; off < 1024; off <<= 1) {
            int t = (tid >= off) ? sh[tid - off] : 0;
            __syncthreads();
            sh[tid] += t;
            __syncthreads();
        }
        int incl = sh[tid];
        if (i < n) g_off[i] = c + incl - v;   // exclusive
        if (tid == 0) s_carry = c + sh[1023];
        __syncthreads();
    }
    if (tid == 0) g_off[n] = s_carry;
}

__global__ void k_invc(int n) {
    int i = blockIdx.x * blockDim.x + threadIdx.x;
    if (i < n) {
        int cnt = g_cnt[i];
        g_invc[i] = 1.0f / (float)(cnt > 0 ? cnt : 1);
    }
}

__global__ void k_scatter(int E) {
    int e = blockIdx.x * blockDim.x + threadIdx.x;
    if (e >= E) return;
    int d = g_dst[e];
    int p = atomicAdd(&g_cur[d], 1);
    g_csr[g_off[d] + p] = g_src[e];
}

// --------------------------- weight split ----------------------------------
// dst[n][k] (k<128: Wl, else Wr) split into bf16 hi + bf16 residual lo.
__global__ void k_cvt_w(const float* __restrict__ Wl, const float* __restrict__ Wr,
                        __nv_bfloat16* __restrict__ dh, __nv_bfloat16* __restrict__ dl,
                        int N) {
    int i = blockIdx.x * blockDim.x + threadIdx.x;
    if (i >= N * 256) return;
    int nrow = i >> 8, k = i & 255;
    float v = (k < 128) ? Wl[nrow * 128 + k] : Wr[nrow * 128 + (k - 128)];
    __nv_bfloat16 h = __float2bfloat16(v);
    dh[i] = h;
    dl[i] = __float2bfloat16(v - __bfloat162float(h));
}

// --------------------------- aggregation (fp32) -----------------------------
// warp-per-node mean of neighbor rows (128 f32 = float4 per lane).
__global__ __launch_bounds__(256) void k_agg(const float* __restrict__ xext,
                                             int insel, int n) {
    const float* xin = (insel == 0) ? xext : (insel == 1) ? g_h1 : g_h2;
    int warp = (blockIdx.x * blockDim.x + threadIdx.x) >> 5;
    int lane = threadIdx.x & 31;
    if (warp >= n) return;
    int s0 = g_off[warp], s1 = g_off[warp + 1];
    const float4* xin4 = (const float4*)xin;
    float4 acc = make_float4(0.f, 0.f, 0.f, 0.f);
    int i = s0;
    for (; i + 1 < s1; i += 2) {
        int a = g_csr[i], b = g_csr[i + 1];
        float4 va = xin4[a * 32 + lane];
        float4 vb = xin4[b * 32 + lane];
        acc.x += va.x + vb.x; acc.y += va.y + vb.y;
        acc.z += va.z + vb.z; acc.w += va.w + vb.w;
    }
    if (i < s1) {
        int a = g_csr[i];
        float4 va = xin4[a * 32 + lane];
        acc.x += va.x; acc.y += va.y; acc.z += va.z; acc.w += va.w;
    }
    float ic = g_invc[warp];
    acc.x *= ic; acc.y *= ic; acc.z *= ic; acc.w *= ic;
    ((float4*)g_mean)[warp * 32 + lane] = acc;
}

// --------------------------- tensor-core GEMM (bf16x3) ----------------------

__device__ __forceinline__ void mma16816(float* c, const unsigned* a, const unsigned* b) {
    asm volatile(
        "mma.sync.aligned.m16n8k16.row.col.f32.bf16.bf16.f32 "
        "{%0,%1,%2,%3}, {%4,%5,%6,%7}, {%8,%9}, {%0,%1,%2,%3};\n"
        : "+f"(c[0]), "+f"(c[1]), "+f"(c[2]), "+f"(c[3])
        : "r"(a[0]), "r"(a[1]), "r"(a[2]), "r"(a[3]), "r"(b[0]), "r"(b[1]));
}
__device__ __forceinline__ void ldsm4(unsigned* r, uint32_t addr) {
    asm volatile("ldmatrix.sync.aligned.m8n8.x4.shared.b16 {%0,%1,%2,%3}, [%4];\n"
        : "=r"(r[0]), "=r"(r[1]), "=r"(r[2]), "=r"(r[3]) : "r"(addr));
}

// out[m][j] = sum_k mean[m][k]*W[j][k] + sum_k Ax[m][k]*W[j][128+k] + bias[j]
// FUSE: + ReLU + LayerNorm. A operands fp32 in gmem, split hi/lo at tile load.
// BM=128, BK=32, 256 threads (8 warps), warp tile m16 x nBN (whole rows).
template <int BN, bool FUSE>
__global__ __launch_bounds__(256) void k_mma(
    const float* __restrict__ Ax,
    const __nv_bfloat16* __restrict__ Wh,      // [BN][256] concat [Wl|Wr] hi
    const __nv_bfloat16* __restrict__ Wl_,     // lo
    const float* __restrict__ bias,
    const float* __restrict__ gamma, const float* __restrict__ beta,
    float* __restrict__ out, int n)
{
    constexpr int BM = 128, BK = 32;
    constexpr int LDA = BK + 8;            // 40 bf16 row stride (80B, 16B-mult)
    constexpr int NT = BN / 8;             // n-tiles per warp row stripe

    __shared__ __align__(16) __nv_bfloat16 Ash[BM * LDA];
    __shared__ __align__(16) __nv_bfloat16 Asl[BM * LDA];
    __shared__ __align__(16) __nv_bfloat16 Bsh[BN * LDA];
    __shared__ __align__(16) __nv_bfloat16 Bsl[BN * LDA];

    const int tid = threadIdx.x;
    const int lane = tid & 31, warp = tid >> 5;
    const int rowBase = blockIdx.x * BM;

    float c[NT][4];
#pragma unroll
    for (int j = 0; j < NT; j++)
#pragma unroll
        for (int q = 0; q < 4; q++) c[j][q] = 0.f;

    const uint32_t ahBase = (uint32_t)__cvta_generic_to_shared(Ash);
    const uint32_t alBase = (uint32_t)__cvta_generic_to_shared(Asl);
    const uint32_t bhBase = (uint32_t)__cvta_generic_to_shared(Bsh);
    const uint32_t blBase = (uint32_t)__cvta_generic_to_shared(Bsl);
    const uint32_t aOff =
        (uint32_t)(((warp * 16 + (lane & 15)) * LDA + ((lane >> 4) << 3)) * 2);
    const int bRow = (lane & 7) + ((lane >> 4) << 3);   // n within 16-tile
    const int bKof = ((lane >> 3) & 1) << 3;            // k offset 0/8

    // 8 K-steps of 32: t=0..3 -> (g_mean, W[:,0:128]); t=4..7 -> (Ax, W[:,128:])
    for (int t = 0; t < 8; t++) {
        const float* A = (t < 4) ? g_mean : Ax;
        const int k0 = (t & 3) * BK;

        // A tile: BM x 32 fp32 -> split to bf16 hi/lo. 8 values per thread-chunk.
#pragma unroll
        for (int i = 0; i < (BM * 4) / 256; i++) {
            int q = tid + i * 256;
            int row = q >> 2, c8 = q & 3;
            float v[8];
            int gr = rowBase + row;
            if (gr < n) {
                float4 v0 = *(const float4*)(A + gr * 128 + k0 + c8 * 8);
                float4 v1 = *(const float4*)(A + gr * 128 + k0 + c8 * 8 + 4);
                v[0] = v0.x; v[1] = v0.y; v[2] = v0.z; v[3] = v0.w;
                v[4] = v1.x; v[5] = v1.y; v[6] = v1.z; v[7] = v1.w;
            } else {
#pragma unroll
                for (int j = 0; j < 8; j++) v[j] = 0.f;
            }
            __nv_bfloat16 h[8], l[8];
#pragma unroll
            for (int j = 0; j < 8; j++) {
                h[j] = __float2bfloat16(v[j]);
                l[j] = __float2bfloat16(v[j] - __bfloat162float(h[j]));
            }
            *(uint4*)(&Ash[row * LDA + c8 * 8]) = *(uint4*)h;
            *(uint4*)(&Asl[row * LDA + c8 * 8]) = *(uint4*)l;
        }
        // B tile: BN x 32 from pre-split weights
#pragma unroll
        for (int i = 0; i < (BN * 4) / 256; i++) {
            int q = tid + i * 256;
            int row = q >> 2, c8 = q & 3;
            *(uint4*)(&Bsh[row * LDA + c8 * 8]) =
                *(const uint4*)(Wh + row * 256 + t * 32 + c8 * 8);
            *(uint4*)(&Bsl[row * LDA + c8 * 8]) =
                *(const uint4*)(Wl_ + row * 256 + t * 32 + c8 * 8);
        }
        __syncthreads();

#pragma unroll
        for (int kk = 0; kk < BK; kk += 16) {
            unsigned ah[4], al[4];
            ldsm4(ah, ahBase + aOff + (uint32_t)(kk * 2));
            ldsm4(al, alBase + aOff + (uint32_t)(kk * 2));
#pragma unroll
            for (int jp = 0; jp < NT / 2; jp++) {
                unsigned bh[4], bl[4];
                uint32_t bo = (uint32_t)(((jp * 16 + bRow) * LDA + kk + bKof) * 2);
                ldsm4(bh, bhBase + bo);
                ldsm4(bl, blBase + bo);
                mma16816(c[2 * jp], ah, bh);
                mma16816(c[2 * jp], ah, bl);
                mma16816(c[2 * jp], al, bh);
                mma16816(c[2 * jp + 1], ah, bh + 2);
                mma16816(c[2 * jp + 1], ah, bl + 2);
                mma16816(c[2 * jp + 1], al, bh + 2);
            }
        }
        __syncthreads();
    }

    // ---- epilogue ----
    const int r0 = rowBase + warp * 16 + (lane >> 2);
    const int r1 = r0 + 8;
    const int cb = (lane & 3) * 2;

    if constexpr (FUSE) {
        float s0 = 0.f, ss0 = 0.f, s1 = 0.f, ss1 = 0.f;
#pragma unroll
        for (int j = 0; j < NT; j++) {
            float b0 = bias[j * 8 + cb], b1 = bias[j * 8 + cb + 1];
            c[j][0] = fmaxf(c[j][0] + b0, 0.f);
            c[j][1] = fmaxf(c[j][1] + b1, 0.f);
            c[j][2] = fmaxf(c[j][2] + b0, 0.f);
            c[j][3] = fmaxf(c[j][3] + b1, 0.f);
            s0 += c[j][0] + c[j][1]; ss0 += c[j][0] * c[j][0] + c[j][1] * c[j][1];
            s1 += c[j][2] + c[j][3]; ss1 += c[j][2] * c[j][2] + c[j][3] * c[j][3];
        }
#pragma unroll
        for (int o = 1; o <= 2; o <<= 1) {
            s0 += __shfl_xor_sync(0xffffffffu, s0, o);
            ss0 += __shfl_xor_sync(0xffffffffu, ss0, o);
            s1 += __shfl_xor_sync(0xffffffffu, s1, o);
            ss1 += __shfl_xor_sync(0xffffffffu, ss1, o);
        }
        const float inv = 1.0f / 128.0f;
        float mu0 = s0 * inv, var0 = ss0 * inv - mu0 * mu0;
        float mu1 = s1 * inv, var1 = ss1 * inv - mu1 * mu1;
        float rs0 = rsqrtf(var0 + 1e-5f);
        float rs1 = rsqrtf(var1 + 1e-5f);
#pragma unroll
        for (int j = 0; j < NT; j++) {
            float g0 = gamma[j * 8 + cb], g1v = gamma[j * 8 + cb + 1];
            float e0 = beta[j * 8 + cb],  e1 = beta[j * 8 + cb + 1];
            if (r0 < n)
                *(float2*)(out + r0 * 128 + j * 8 + cb) = make_float2(
                    (c[j][0] - mu0) * rs0 * g0 + e0,
                    (c[j][1] - mu0) * rs0 * g1v + e1);
            if (r1 < n)
                *(float2*)(out + r1 * 128 + j * 8 + cb) = make_float2(
                    (c[j][2] - mu1) * rs1 * g0 + e0,
                    (c[j][3] - mu1) * rs1 * g1v + e1);
        }
    } else {
#pragma unroll
        for (int j = 0; j < NT; j++) {
            float b0 = bias[j * 8 + cb], b1 = bias[j * 8 + cb + 1];
            if (r0 < n)
                *(float2*)(out + r0 * BN + j * 8 + cb) =
                    make_float2(c[j][0] + b0, c[j][1] + b1);
            if (r1 < n)
                *(float2*)(out + r1 * BN + j * 8 + cb) =
                    make_float2(c[j][2] + b0, c[j][3] + b1);
        }
    }
}

// --------------------------- launch ----------------------------------------

extern "C" void kernel_launch(void* const* d_in, const int* in_sizes, int n_in,
                              void* d_out, int out_size)
{
    const float* x   = (const float*)d_in[0];
    const void*  ei  = d_in[1];
    const float* Wl1 = (const float*)d_in[2];
    const float* bl1 = (const float*)d_in[3];
    const float* Wr1 = (const float*)d_in[4];
    const float* Wl2 = (const float*)d_in[5];
    const float* bl2 = (const float*)d_in[6];
    const float* Wr2 = (const float*)d_in[7];
    const float* Wl3 = (const float*)d_in[8];
    const float* bl3 = (const float*)d_in[9];
    const float* Wr3 = (const float*)d_in[10];
    const float* g1  = (const float*)d_in[11];
    const float* be1 = (const float*)d_in[12];
    const float* g2  = (const float*)d_in[13];
    const float* be2 = (const float*)d_in[14];

    const int n = in_sizes[0] / C;       // 50000
    const int E = in_sizes[1] / 2;       // 800000

    const int TB = 256;
    // ---- CSR build + weight split ----
    k_detect<<<1, TB>>>((const unsigned*)ei);
    k_convert<<<(E + TB - 1) / TB, TB>>>(ei, E);
    k_zero<<<(n + TB - 1) / TB, TB>>>(n);
    k_hist<<<(E + TB - 1) / TB, TB>>>(E);
    k_scan<<<1, 1024>>>(n);
    k_invc<<<(n + TB - 1) / TB, TB>>>(n);
    k_scatter<<<(E + TB - 1) / TB, TB>>>(E);

    __nv_bfloat16 *w1h, *w1l, *w2h, *w2l, *w3h, *w3l;
    cudaGetSymbolAddress((void**)&w1h, g_w1h);
    cudaGetSymbolAddress((void**)&w1l, g_w1l);
    cudaGetSymbolAddress((void**)&w2h, g_w2h);
    cudaGetSymbolAddress((void**)&w2l, g_w2l);
    cudaGetSymbolAddress((void**)&w3h, g_w3h);
    cudaGetSymbolAddress((void**)&w3l, g_w3l);
    k_cvt_w<<<(128 * 256 + TB - 1) / TB, TB>>>(Wl1, Wr1, w1h, w1l, 128);
    k_cvt_w<<<(128 * 256 + TB - 1) / TB, TB>>>(Wl2, Wr2, w2h, w2l, 128);
    k_cvt_w<<<(64 * 256 + TB - 1) / TB, TB>>>(Wl3, Wr3, w3h, w3l, 64);

    float *h1p, *h2p;
    cudaGetSymbolAddress((void**)&h1p, g_h1);
    cudaGetSymbolAddress((void**)&h2p, g_h2);

    const int aggGrid  = (n + 7) / 8;       // 8 warps/block, warp per node
    const int gemmGrid = (n + 127) / 128;

    // ---- layer 1 ----
    k_agg<<<aggGrid, TB>>>(x, 0, n);
    k_mma<128, true><<<gemmGrid, TB>>>(x, w1h, w1l, bl1, g1, be1, h1p, n);
    // ---- layer 2 ----
    k_agg<<<aggGrid, TB>>>(x, 1, n);
    k_mma<128, true><<<gemmGrid, TB>>>(h1p, w2h, w2l, bl2, g2, be2, h2p, n);
    // ---- layer 3 (64 outputs, no ReLU/LN) ----
    k_agg<<<aggGrid, TB>>>(x, 2, n);
    k_mma<64, false><<<gemmGrid, TB>>>(h2p, w3h, w3l, bl3, nullptr, nullptr,
                                       (float*)d_out, n);
}